// round 10
// baseline (speedup 1.0000x reference)
#include <cuda_runtime.h>
#include <cstdint>
#include <cstddef>

#define TSTEPS 16384
#define BATCH  32
#define HID    96
#define UNITS_PER_CTA 48       // rank r owns units [48r, 48r+48)
#define NCOMP  192             // 48 units * 4 gates
#define NTH    224             // 6 compute warps + 1 aux warp
#define NWARPS 7
#define EXPECTED_ARRIVALS (2 * (NWARPS * 32 + UNITS_PER_CTA))   // 544

// smem layout (floats): xs[16384] | hb[2][96] | (then 8B mbar, 16B aligned)
#define SMEM_FLOATS (TSTEPS + 2 * HID + 8)
#define SMEM_BYTES  (SMEM_FLOATS * sizeof(float))
#define MBAR_OFF    ((TSTEPS + 2 * HID) * 4)     // byte offset of mbarrier

__device__ __forceinline__ float tanh_fast(float x) {
    float y;
    asm("tanh.approx.f32 %0, %1;" : "=f"(y) : "f"(x));
    return y;
}
__device__ __forceinline__ uint32_t smem_u32(const void* p) {
    uint32_t a;
    asm("{ .reg .u64 t; cvta.to.shared.u64 t, %1; cvt.u32.u64 %0, t; }"
        : "=r"(a) : "l"(p));
    return a;
}
__device__ __forceinline__ uint32_t mapa_u32(uint32_t a, uint32_t rank) {
    uint32_t r;
    asm("mapa.shared::cluster.u32 %0, %1, %2;" : "=r"(r) : "r"(a), "r"(rank));
    return r;
}
__device__ __forceinline__ void sts_remote_f32(uint32_t addr, float v) {
    asm volatile("st.shared::cluster.f32 [%0], %1;" :: "r"(addr), "f"(v) : "memory");
}
__device__ __forceinline__ void mbar_init(uint32_t a, uint32_t cnt) {
    asm volatile("mbarrier.init.shared.b64 [%0], %1;" :: "r"(a), "r"(cnt) : "memory");
}
__device__ __forceinline__ void mbar_arrive_local(uint32_t a, uint32_t cnt) {
    asm volatile("mbarrier.arrive.release.cta.shared::cta.b64 _, [%0], %1;"
                 :: "r"(a), "r"(cnt) : "memory");
}
__device__ __forceinline__ void mbar_arrive_remote(uint32_t a, uint32_t cnt) {
    asm volatile("mbarrier.arrive.release.cluster.shared::cluster.b64 _, [%0], %1;"
                 :: "r"(a), "r"(cnt) : "memory");
}
__device__ __forceinline__ void mbar_wait(uint32_t a, uint32_t parity) {
    uint32_t done;
    asm volatile("{\n\t.reg .pred p;\n\t"
        "mbarrier.try_wait.parity.acquire.cluster.shared::cta.b64 p, [%1], %2;\n\t"
        "selp.b32 %0, 1, 0, p;\n\t}"
        : "=r"(done) : "r"(a), "r"(parity) : "memory");
    if (!done) {
        asm volatile("{\n\t.reg .pred P1;\n\t"
            "W_%=:\n\t"
            "mbarrier.try_wait.parity.acquire.cluster.shared::cta.b64 P1, [%0], %1, 0x989680;\n\t"
            "@P1 bra.uni D_%=;\n\t"
            "bra.uni W_%=;\n\t"
            "D_%=:\n\t}"
            :: "r"(a), "r"(parity) : "memory");
    }
}
__device__ __forceinline__ void cluster_sync_inline() {
    asm volatile("barrier.cluster.arrive.aligned;" ::: "memory");
    asm volatile("barrier.cluster.wait.aligned;" ::: "memory");
}

__global__ void __launch_bounds__(NTH, 1) __cluster_dims__(2, 1, 1)
lstm_cluster(const float* __restrict__ x,
             const float* __restrict__ w_ih,
             const float* __restrict__ w_hh,
             const float* __restrict__ b_ih,
             const float* __restrict__ b_hh,
             const float* __restrict__ fc_w,
             const float* __restrict__ fc_b,
             float* __restrict__ out)
{
    extern __shared__ float smem[];
    float* xs  = smem;                  // [TSTEPS]
    float* hb0 = smem + TSTEPS;         // [HID] buffer 0 (full 96-unit mirror)
    float* hb1 = hb0 + HID;             // [HID] buffer 1

    const int tid  = threadIdx.x;
    const int b    = blockIdx.x >> 1;   // batch element
    const int rank = blockIdx.x & 1;    // cluster rank (also cluster_ctarank)

    const uint32_t mbar_local = smem_u32(smem) + MBAR_OFF;
    const uint32_t hb0_loc    = smem_u32(hb0);
    const uint32_t hb1_loc    = smem_u32(hb1);
    const uint32_t peer       = rank ^ 1u;
    const uint32_t mbar_rem   = mapa_u32(mbar_local, peer);
    const uint32_t hb0_rem    = mapa_u32(hb0_loc, peer);
    const uint32_t hb1_rem    = mapa_u32(hb1_loc, peer);

    // Stage x[:, b] into shared.
    for (int t = tid; t < TSTEPS; t += NTH)
        xs[t] = x[(size_t)t * BATCH + b];

    // ---- per-thread persistent state ----
    unsigned long long w2[48];          // full 96-wide W_hh row as 48 f32x2
    float wih = 0.f, bias = 0.f, c = 0.f;
    float act_a = 0.5f, act_s = 0.5f, act_b = 0.5f;   // sigmoid = 0.5*tanh(0.5x)+0.5
    float fw0 = 0.f, fw1 = 0.f, fw2 = 0.f, fcb = 0.f;
    int gu = 0;                          // global unit owned by this quad

    if (tid < NCOMP) {
        gu = UNITS_PER_CTA * rank + (tid >> 2);
        const int q   = tid & 3;         // 0=i,1=f,2=g,3=o
        const int row = q * HID + gu;
        const unsigned long long* wrow =
            reinterpret_cast<const unsigned long long*>(w_hh + row * HID);
        #pragma unroll
        for (int k = 0; k < 48; ++k) w2[k] = wrow[k];
        wih  = __ldg(w_ih + row);
        bias = __ldg(b_ih + row) + __ldg(b_hh + row);
        if (q == 2) { act_a = 1.f; act_s = 1.f; act_b = 0.f; }
    } else {
        const int l = tid - NCOMP;       // aux warp: fc weights, 3 per lane
        fw0 = fc_w[l]; fw1 = fc_w[l + 32]; fw2 = fc_w[l + 64];
        fcb = fc_b[0];
    }
    if (tid < HID) hb0[tid] = 0.f;       // h0 = 0 (read buffer at t=0)
    if (tid == 0)  mbar_init(mbar_local, EXPECTED_ARRIVALS);
    __syncthreads();
    cluster_sync_inline();               // mbar + h0 visible cluster-wide

    float*   h_rd     = hb0;
    uint32_t hwr_loc  = hb1_loc;         // local write buffer (byte addr)
    uint32_t hwr_rem  = hb1_rem;         // peer's mirror of the write buffer
    uint32_t hrd_swap = hb0_loc, hrd_swap_r = hb0_rem;  // for pointer swapping

    const bool is_leader = (tid < NCOMP) && ((tid & 3) == 0);

    #pragma unroll 1
    for (int t = 0; t < TSTEPS; ++t) {
        if (tid < NCOMP) {
            const float gx = fmaf(xs[t], wih, bias);

            // full 96-wide dot via packed FFMA2, 4 chains (reads the mirror)
            const ulonglong2* hv = reinterpret_cast<const ulonglong2*>(h_rd);
            unsigned long long a0 = 0ull, a1 = 0ull, a2 = 0ull, a3 = 0ull;
            #pragma unroll
            for (int k = 0; k < 12; ++k) {
                ulonglong2 p = hv[2 * k];
                ulonglong2 r = hv[2 * k + 1];
                asm("fma.rn.f32x2 %0, %1, %2, %0;" : "+l"(a0) : "l"(w2[4*k+0]), "l"(p.x));
                asm("fma.rn.f32x2 %0, %1, %2, %0;" : "+l"(a1) : "l"(w2[4*k+1]), "l"(p.y));
                asm("fma.rn.f32x2 %0, %1, %2, %0;" : "+l"(a2) : "l"(w2[4*k+2]), "l"(r.x));
                asm("fma.rn.f32x2 %0, %1, %2, %0;" : "+l"(a3) : "l"(w2[4*k+3]), "l"(r.y));
            }
            asm("add.rn.f32x2 %0, %0, %1;" : "+l"(a0) : "l"(a1));
            asm("add.rn.f32x2 %0, %0, %1;" : "+l"(a2) : "l"(a3));
            asm("add.rn.f32x2 %0, %0, %1;" : "+l"(a0) : "l"(a2));
            unsigned lo, hi;
            asm("mov.b64 {%0,%1}, %2;" : "=r"(lo), "=r"(hi) : "l"(a0));
            float g   = __uint_as_float(lo) + __uint_as_float(hi) + gx;
            float act = fmaf(tanh_fast(g * act_a), act_s, act_b);

            // cell update via quad shuffles
            const unsigned m = 0xffffffffu;
            float gi = __shfl_sync(m, act, 0, 4);
            float gf = __shfl_sync(m, act, 1, 4);
            float gg = __shfl_sync(m, act, 2, 4);
            float go = __shfl_sync(m, act, 3, 4);
            c = fmaf(gf, c, gi * gg);
            float h = go * tanh_fast(c);

            if (is_leader) {
                // publish h_t locally and to the peer's mirror, then arrive
                reinterpret_cast<float*>(0)[0];  // (no-op placeholder removed below)
            }
            if ((tid & 3) == 0) {
                *reinterpret_cast<float*>(
                    reinterpret_cast<char*>(smem) + (hwr_loc - smem_u32(smem))) ;
            }
            // --- leader publication (explicit addresses) ---
            if ((tid & 3) == 0) {
                // local store
                asm volatile("st.shared.f32 [%0], %1;"
                             :: "r"(hwr_loc + 4u * (uint32_t)gu), "f"(h) : "memory");
                // remote store into peer's mirror
                sts_remote_f32(hwr_rem + 4u * (uint32_t)gu, h);
                mbar_arrive_local(mbar_local, 1);
                mbar_arrive_remote(mbar_rem, 1);
            }
        } else if (t > 0 && (((t - 1) & 1) == rank)) {
            // aux warp (parity-split across ranks): out[t-1] from h_{t-1}
            const int l = tid - NCOMP;
            float p = fw0 * h_rd[l] + fw1 * h_rd[l + 32] + fw2 * h_rd[l + 64];
            #pragma unroll
            for (int off = 16; off > 0; off >>= 1)
                p += __shfl_xor_sync(0xffffffffu, p, off);
            if (l == 0)
                out[(size_t)(t - 1) * BATCH + b] = p + fcb + xs[t - 1];
        }

        // per-warp completion arrivals (reads of step t are done)
        __syncwarp();
        if ((tid & 31) == 0) {
            mbar_arrive_local(mbar_local, 32);
            mbar_arrive_remote(mbar_rem, 32);
        }
        mbar_wait(mbar_local, t & 1);

        // swap read/write buffers (both local ptr and byte addresses)
        {
            float* nrd = (h_rd == hb0) ? hb1 : hb0;
            h_rd = nrd;
            uint32_t tmp  = hwr_loc;  hwr_loc  = hrd_swap;   hrd_swap   = tmp;
            uint32_t tmpr = hwr_rem;  hwr_rem  = hrd_swap_r; hrd_swap_r = tmpr;
        }
    }

    // final output: s = T-1, owned by rank (T-1)&1 = 1; h_rd holds h_{T-1}
    if (rank == ((TSTEPS - 1) & 1) && tid >= NCOMP) {
        const int l = tid - NCOMP;
        float p = fw0 * h_rd[l] + fw1 * h_rd[l + 32] + fw2 * h_rd[l + 64];
        #pragma unroll
        for (int off = 16; off > 0; off >>= 1)
            p += __shfl_xor_sync(0xffffffffu, p, off);
        if (l == 0)
            out[(size_t)(TSTEPS - 1) * BATCH + b] = p + fcb + xs[TSTEPS - 1];
    }

    cluster_sync_inline();   // keep smem alive until peer's last stores land
}

extern "C" void kernel_launch(void* const* d_in, const int* in_sizes, int n_in,
                              void* d_out, int out_size)
{
    const float* x    = (const float*)d_in[0];
    const float* w_ih = (const float*)d_in[1];
    const float* w_hh = (const float*)d_in[2];
    const float* b_ih = (const float*)d_in[3];
    const float* b_hh = (const float*)d_in[4];
    const float* fc_w = (const float*)d_in[5];
    const float* fc_b = (const float*)d_in[6];
    float* out = (float*)d_out;

    cudaFuncSetAttribute(lstm_cluster,
                         cudaFuncAttributeMaxDynamicSharedMemorySize,
                         (int)SMEM_BYTES);
    // __cluster_dims__(2,1,1) is baked into the kernel; plain launch honors it.
    lstm_cluster<<<2 * BATCH, NTH, SMEM_BYTES>>>(x, w_ih, w_hh, b_ih, b_hh,
                                                 fc_w, fc_b, out);
}

// round 12
// speedup vs baseline: 1.7425x; 1.7425x over previous
#include <cuda_runtime.h>
#include <cstdint>
#include <cstddef>

#define TSTEPS 16384
#define BATCH  32
#define HID    96
#define GATES  384
#define NTH    416   // 12 compute warps + 1 aux (output) warp
#define SMEM_FLOATS (TSTEPS + 2 * HID + 8)
#define SMEM_BYTES  (SMEM_FLOATS * sizeof(float))

__device__ __forceinline__ float tanh_fast(float x) {
    float y;
    asm("tanh.approx.f32 %0, %1;" : "=f"(y) : "f"(x));   // MUFU.TANH
    return y;
}

struct ThreadState {
    unsigned long long w2[48];   // W_hh row as 48 packed f32x2
    float wih, bias, c;
    float act_a, act_s, act_b;   // sigmoid = 0.5*tanh(0.5x)+0.5 ; tanh = 1*tanh(1x)+0
    float fw0, fw1, fw2, fcb;
    int   u;                     // unit owned by this quad
};

// One LSTM step. h_rd: h_{t-1} (read), h_wr: h_t (written by quad leaders).
// gx_cur was precomputed; gx for t+1 is returned (computed off the critical tail).
__device__ __forceinline__ float lstm_step(
    int t, const float* __restrict__ h_rd, float* __restrict__ h_wr,
    const float* __restrict__ xs, float* __restrict__ out,
    ThreadState& s, int tid, int b, float gx_cur)
{
    float gx_next = 0.f;
    if (tid < GATES) {
        // prefetch next step's gx during the matvec window (independent of h)
        gx_next = fmaf(xs[t + 1], s.wih, s.bias);

        // ---- dot(W_hh[row], h_{t-1}) via packed FFMA2, 4 chains ----
        // acc0 seeded with (gx, 0): final sum = lo + hi already includes gx.
        const ulonglong2* hv = reinterpret_cast<const ulonglong2*>(h_rd);
        unsigned long long a0 = (unsigned long long)__float_as_uint(gx_cur);
        unsigned long long a1 = 0ull, a2 = 0ull, a3 = 0ull;
        #pragma unroll
        for (int k = 0; k < 12; ++k) {
            ulonglong2 p = hv[2 * k];
            ulonglong2 r = hv[2 * k + 1];
            asm("fma.rn.f32x2 %0, %1, %2, %0;" : "+l"(a0) : "l"(s.w2[4*k+0]), "l"(p.x));
            asm("fma.rn.f32x2 %0, %1, %2, %0;" : "+l"(a1) : "l"(s.w2[4*k+1]), "l"(p.y));
            asm("fma.rn.f32x2 %0, %1, %2, %0;" : "+l"(a2) : "l"(s.w2[4*k+2]), "l"(r.x));
            asm("fma.rn.f32x2 %0, %1, %2, %0;" : "+l"(a3) : "l"(s.w2[4*k+3]), "l"(r.y));
        }
        asm("add.rn.f32x2 %0, %0, %1;" : "+l"(a0) : "l"(a1));
        asm("add.rn.f32x2 %0, %0, %1;" : "+l"(a2) : "l"(a3));
        asm("add.rn.f32x2 %0, %0, %1;" : "+l"(a0) : "l"(a2));
        unsigned lo, hi;
        asm("mov.b64 {%0,%1}, %2;" : "=r"(lo), "=r"(hi) : "l"(a0));
        float g   = __uint_as_float(lo) + __uint_as_float(hi);
        float act = fmaf(tanh_fast(g * s.act_a), s.act_s, s.act_b);

        // ---- leader-only cell update: gather f,g,o with 3 quad shuffles ----
        const unsigned m = 0xffffffffu;
        float vf = __shfl_sync(m, act, 1, 4);
        float vg = __shfl_sync(m, act, 2, 4);
        float vo = __shfl_sync(m, act, 3, 4);
        if ((tid & 3) == 0) {              // leader: act == sigmoid(i); c leader-only
            s.c = fmaf(vf, s.c, act * vg);
            h_wr[s.u] = vo * tanh_fast(s.c);
        }
    } else if (t > 0) {
        // aux warp: out[t-1] = fc_w . h_{t-1} + fc_b + x[t-1]
        const int l = tid - GATES;
        float p = s.fw0 * h_rd[l] + s.fw1 * h_rd[l + 32] + s.fw2 * h_rd[l + 64];
        #pragma unroll
        for (int off = 16; off > 0; off >>= 1)
            p += __shfl_xor_sync(0xffffffffu, p, off);
        if (l == 0)
            out[(size_t)(t - 1) * BATCH + b] = p + s.fcb + xs[t - 1];
    }
    __syncthreads();                       // h_t published; h_rd free for reuse
    return gx_next;
}

__global__ void __launch_bounds__(NTH, 1)
lstm_persist(const float* __restrict__ x,
             const float* __restrict__ w_ih,
             const float* __restrict__ w_hh,
             const float* __restrict__ b_ih,
             const float* __restrict__ b_hh,
             const float* __restrict__ fc_w,
             const float* __restrict__ fc_b,
             float* __restrict__ out)
{
    extern __shared__ float smem[];
    float* xs  = smem;                   // [TSTEPS] x column for this batch elem
    float* hb0 = smem + TSTEPS;          // [HID] buffer A (h_{even} read)
    float* hb1 = hb0 + HID;              // [HID] buffer B

    const int tid = threadIdx.x;
    const int b   = blockIdx.x;          // one CTA / batch element / SM

    // Stage x[:, b] into shared (one-time).
    for (int t = tid; t < TSTEPS; t += NTH)
        xs[t] = x[(size_t)t * BATCH + b];

    ThreadState s;
    s.wih = 0.f; s.bias = 0.f; s.c = 0.f;
    s.act_a = 0.5f; s.act_s = 0.5f; s.act_b = 0.5f;
    s.fw0 = 0.f; s.fw1 = 0.f; s.fw2 = 0.f; s.fcb = 0.f;
    s.u = 0;

    if (tid < GATES) {
        // quad-interleaved: unit u = tid>>2, gate q = tid&3 (0=i,1=f,2=g,3=o)
        s.u = tid >> 2;
        const int q   = tid & 3;
        const int row = q * HID + s.u;
        const unsigned long long* wrow =
            reinterpret_cast<const unsigned long long*>(w_hh + row * HID);
        #pragma unroll
        for (int k = 0; k < 48; ++k) s.w2[k] = wrow[k];
        s.wih  = __ldg(w_ih + row);
        s.bias = __ldg(b_ih + row) + __ldg(b_hh + row);
        if (q == 2) { s.act_a = 1.f; s.act_s = 1.f; s.act_b = 0.f; } // g: plain tanh
    } else {
        const int l = tid - GATES;       // aux warp: fc weights, 3 per lane
        s.fw0 = fc_w[l]; s.fw1 = fc_w[l + 32]; s.fw2 = fc_w[l + 64];
        s.fcb = fc_b[0];
    }
    if (tid < HID) hb0[tid] = 0.f;       // h0 = 0 (read buffer at t=0); c0=0 in regs
    __syncthreads();

    // First gx precomputed outside the loop.
    float gx = (tid < GATES) ? fmaf(xs[0], s.wih, s.bias) : 0.f;

    // 2x-unrolled main loop: even step hb0->hb1, odd step hb1->hb0.
    #pragma unroll 1
    for (int t = 0; t < TSTEPS; t += 2) {
        gx = lstm_step(t,     hb0, hb1, xs, out, s, tid, b, gx);
        gx = lstm_step(t + 1, hb1, hb0, xs, out, s, tid, b, gx);
    }
    // note: the last gx reads xs[TSTEPS] == hb0[0] (in-bounds smem, value unused).

    // Final output for t = TSTEPS-1: step 16383 (odd) wrote h into hb0.
    if (tid >= GATES) {
        const int l = tid - GATES;
        float p = s.fw0 * hb0[l] + s.fw1 * hb0[l + 32] + s.fw2 * hb0[l + 64];
        #pragma unroll
        for (int off = 16; off > 0; off >>= 1)
            p += __shfl_xor_sync(0xffffffffu, p, off);
        if (l == 0)
            out[(size_t)(TSTEPS - 1) * BATCH + b] = p + s.fcb + xs[TSTEPS - 1];
    }
}

extern "C" void kernel_launch(void* const* d_in, const int* in_sizes, int n_in,
                              void* d_out, int out_size)
{
    const float* x    = (const float*)d_in[0];
    const float* w_ih = (const float*)d_in[1];
    const float* w_hh = (const float*)d_in[2];
    const float* b_ih = (const float*)d_in[3];
    const float* b_hh = (const float*)d_in[4];
    const float* fc_w = (const float*)d_in[5];
    const float* fc_b = (const float*)d_in[6];
    float* out = (float*)d_out;

    cudaFuncSetAttribute(lstm_persist,
                         cudaFuncAttributeMaxDynamicSharedMemorySize,
                         (int)SMEM_BYTES);
    lstm_persist<<<BATCH, NTH, SMEM_BYTES>>>(x, w_ih, w_hh, b_ih, b_hh,
                                             fc_w, fc_b, out);
}